// round 16
// baseline (speedup 1.0000x reference)
#include <cuda_runtime.h>
#include <cuda_fp16.h>
#include <stdint.h>

#define S_LEN 4096
#define D_DIM 64
#define BH    16
#define QT    128
#define KT    128
#define NKT   (S_LEN / KT)
#define NTHR  128
#define RSB   144           // smem row stride (bytes), 16B-aligned, conflict-free for ldmatrix

// smem (bytes): Qh[128][72h] | 2 x { Kh[128][72h] | Vh[128][72h] }
#define SMQ_H   0
#define SMKV    (128 * RSB)
#define KVB     (2 * 128 * RSB)         // 36864 bytes per buffer
#define SM_TOTAL (SMKV + 2 * KVB)       // 92160

// Q pre-scaled by 0.125*log2(e): S = Qs*K^T is already the exp2 argument.
#define EXPC 0.18033688011112042f

// fp16-converted inputs (prologue-filled); mask as additive fp16 bias (0 or -20000)
__device__ __half  g_Qh[(size_t)BH * S_LEN * D_DIM];
__device__ __half  g_Kh[(size_t)BH * S_LEN * D_DIM];
__device__ __half  g_Vh[(size_t)BH * S_LEN * D_DIM];
__device__ __half  g_maskb[(size_t)S_LEN * S_LEN];

// ---------------- helpers ----------------
__device__ __forceinline__ uint32_t su32(const void* p) {
    uint32_t a;
    asm("{ .reg .u64 t; cvta.to.shared.u64 t, %1; cvt.u32.u64 %0, t; }" : "=r"(a) : "l"(p));
    return a;
}
__device__ __forceinline__ void cpa16(uint32_t dst, const void* src) {
    asm volatile("cp.async.cg.shared.global [%0], [%1], 16;" :: "r"(dst), "l"(src));
}
#define CPA_COMMIT() asm volatile("cp.async.commit_group;" ::: "memory")
#define CPA_WAIT(n)  asm volatile("cp.async.wait_group %0;" :: "n"(n) : "memory")

__device__ __forceinline__ void ldsm4(uint32_t& r0, uint32_t& r1, uint32_t& r2, uint32_t& r3, uint32_t a) {
    asm volatile("ldmatrix.sync.aligned.m8n8.x4.shared.b16 {%0,%1,%2,%3}, [%4];"
                 : "=r"(r0), "=r"(r1), "=r"(r2), "=r"(r3) : "r"(a));
}
__device__ __forceinline__ void ldsm4t(uint32_t& r0, uint32_t& r1, uint32_t& r2, uint32_t& r3, uint32_t a) {
    asm volatile("ldmatrix.sync.aligned.m8n8.x4.trans.shared.b16 {%0,%1,%2,%3}, [%4];"
                 : "=r"(r0), "=r"(r1), "=r"(r2), "=r"(r3) : "r"(a));
}
__device__ __forceinline__ void mma16816(float* c, const uint32_t* a, uint32_t b0, uint32_t b1) {
    asm volatile("mma.sync.aligned.m16n8k16.row.col.f32.f16.f16.f32 "
                 "{%0,%1,%2,%3},{%4,%5,%6,%7},{%8,%9},{%0,%1,%2,%3};"
                 : "+f"(c[0]), "+f"(c[1]), "+f"(c[2]), "+f"(c[3])
                 : "r"(a[0]), "r"(a[1]), "r"(a[2]), "r"(a[3]), "r"(b0), "r"(b1));
}
__device__ __forceinline__ float ex2f(float x) {
    float r;
    asm("ex2.approx.f32 %0, %1;" : "=f"(r) : "f"(x));
    return r;
}

// ---------------- fused prologue: cvt (blocks 0..4095) + mask bias (rest) ----------------
#define CVT_BLKS 4096
__global__ void prep(const float* __restrict__ Q, const float* __restrict__ K,
                     const float* __restrict__ V, const int* __restrict__ m) {
    if (blockIdx.x < CVT_BLKS) {
        size_t i = (size_t)blockIdx.x * 256 + threadIdx.x;   // over BH*S*D/4
        float4 q = ((const float4*)Q)[i];
        float4 k = ((const float4*)K)[i];
        float4 v = ((const float4*)V)[i];
        ((__half2*)g_Qh)[2*i]   = __floats2half2_rn(q.x * EXPC, q.y * EXPC);
        ((__half2*)g_Qh)[2*i+1] = __floats2half2_rn(q.z * EXPC, q.w * EXPC);
        ((__half2*)g_Kh)[2*i]   = __floats2half2_rn(k.x, k.y);
        ((__half2*)g_Kh)[2*i+1] = __floats2half2_rn(k.z, k.w);
        ((__half2*)g_Vh)[2*i]   = __floats2half2_rn(v.x, v.y);
        ((__half2*)g_Vh)[2*i+1] = __floats2half2_rn(v.z, v.w);
    } else {
        size_t i = (size_t)(blockIdx.x - CVT_BLKS) * 256 + threadIdx.x;   // over S*S/4
        int4 v = ((const int4*)m)[i];
        const __half zz = __float2half(0.f), bb = __float2half(-20000.f);
        ((__half2*)g_maskb)[2*i]   = __halves2half2(v.x ? bb : zz, v.y ? bb : zz);
        ((__half2*)g_maskb)[2*i+1] = __halves2half2(v.z ? bb : zz, v.w ? bb : zz);
    }
}

// ---- main: FA2-style mma.sync, 4 warps x 32 q-rows, KT=128, 8 fused stages ----
__global__ void __launch_bounds__(NTHR, 2)
attn_mma(float* __restrict__ Og)
{
    extern __shared__ __align__(128) char smem[];
    const uint32_t sb = su32(smem);
    const int tid = threadIdx.x, wid = tid >> 5, lane = tid & 31;
    const int g = lane >> 2, qp = lane & 3;
    const int bh = blockIdx.x;
    const int q0 = blockIdx.y * QT;
    const int qw = wid * 32;                  // warp's q-row base (2 m-blocks of 16)

    // ---- issue Q stage (group 0) ----
    #pragma unroll
    for (int i = 0; i < 8; i++) {
        int cid = i * NTHR + tid;             // 0..1023
        int rr = (cid >> 3) & 127, ch = cid & 7;
        const void* src = g_Qh + ((size_t)(bh * S_LEN + q0 + rr)) * D_DIM + ch * 8;
        cpa16(sb + SMQ_H + rr * RSB + ch * 16, src);
    }
    CPA_COMMIT();
    // ---- issue KV tile 0 (group 1): Kh[128] + Vh[128] ----
    #pragma unroll
    for (int i = 0; i < 16; i++) {
        int cid = i * NTHR + tid;             // 0..2047
        int a = cid >> 10, rr = (cid >> 3) & 127, ch = cid & 7;
        const __half* gk = a ? g_Vh : g_Kh;
        const void* src = gk + ((size_t)(bh * S_LEN + rr)) * D_DIM + ch * 8;
        cpa16(sb + SMKV + a * (128 * RSB) + rr * RSB + ch * 16, src);
    }
    CPA_COMMIT();
    CPA_WAIT(1);                              // Q ready
    __syncthreads();

    // ---- Qh fragments (2 m-blocks) register-resident for the whole kernel ----
    const int arow = lane & 15, acolb = (lane >> 4) * 16;
    uint32_t Qh[2][4][4];
    #pragma unroll
    for (int mb = 0; mb < 2; mb++) {
        const uint32_t qa_base = sb + (qw + mb * 16 + arow) * RSB + acolb;
        #pragma unroll
        for (int kc = 0; kc < 4; kc++)
            ldsm4(Qh[mb][kc][0], Qh[mb][kc][1], Qh[mb][kc][2], Qh[mb][kc][3],
                  qa_base + SMQ_H + kc * 32);
    }

    // lane offsets for K (B-frag, non-trans) and V (B-frag, trans)
    const int krow = (lane & 7) + ((lane >> 4) & 1) * 8;
    const int kcolb = ((lane >> 3) & 1) * 16;
    const int vrow = (lane & 7) + ((lane >> 3) & 1) * 8;
    const int vcolb = ((lane >> 4) & 1) * 16;

    float o[2][8][4];
    #pragma unroll
    for (int mb = 0; mb < 2; mb++)
        #pragma unroll
        for (int n = 0; n < 8; n++)
            #pragma unroll
            for (int j = 0; j < 4; j++) o[mb][n][j] = 0.f;
    float lac[2][2] = {{0.f, 0.f}, {0.f, 0.f}};

    // mask bias row pointers: r = mb*2 + half -> q-row qw + 8r + g
    const __half* mrow[4];
    #pragma unroll
    for (int r = 0; r < 4; r++)
        mrow[r] = g_maskb + (size_t)(q0 + qw + 8 * r + g) * S_LEN + 2 * qp;

    #pragma unroll 1
    for (int kt = 0; kt < NKT; kt++) {
        const int kb = kt * KT;
        const uint32_t kvb = sb + SMKV + (kt & 1) * KVB;
        const uint32_t vb  = kvb + 128 * RSB;

        CPA_WAIT(0);        // tile kt resident
        __syncthreads();    // + everyone done reading the buffer we refill next

        // issue next tile AFTER the barrier (single barrier per tile)
        if (kt + 1 < NKT) {
            #pragma unroll
            for (int i = 0; i < 16; i++) {
                int cid = i * NTHR + tid;
                int a = cid >> 10, rr = (cid >> 3) & 127, ch = cid & 7;
                const __half* gk = a ? g_Vh : g_Kh;
                const void* src = gk + ((size_t)(bh * S_LEN + kb + KT + rr)) * D_DIM + ch * 8;
                cpa16(sb + SMKV + ((kt + 1) & 1) * KVB + a * (128 * RSB) + rr * RSB + ch * 16, src);
            }
            CPA_COMMIT();
        }

        // mask double-buffer: stage 0 of this tile
        uint32_t mc[4][2], mn[4][2];
        #pragma unroll
        for (int r = 0; r < 4; r++) {
            mc[r][0] = *(const uint32_t*)(mrow[r] + kb);
            mc[r][1] = *(const uint32_t*)(mrow[r] + kb + 8);
        }

        // ---- 8 fused stages; K/V fragments shared by both m-blocks ----
        #pragma unroll
        for (int j = 0; j < 8; j++) {
            // K fragments for key-block j, all 4 d-chunks
            uint32_t kf[16];
            #pragma unroll
            for (int kc = 0; kc < 4; kc++)
                ldsm4(kf[4*kc], kf[4*kc+1], kf[4*kc+2], kf[4*kc+3],
                      kvb + (16 * j + krow) * RSB + kc * 32 + kcolb);

            // prefetch next stage's mask bias (hides under the MMAs below)
            if (j < 7) {
                #pragma unroll
                for (int r = 0; r < 4; r++) {
                    mn[r][0] = *(const uint32_t*)(mrow[r] + kb + 16 * (j + 1));
                    mn[r][1] = *(const uint32_t*)(mrow[r] + kb + 16 * (j + 1) + 8);
                }
            }

            // S then P for both m-blocks of this key-block
            uint32_t Phi[2][4];
            #pragma unroll
            for (int mb = 0; mb < 2; mb++) {
                float s0[4] = {0.f, 0.f, 0.f, 0.f};
                float s1[4] = {0.f, 0.f, 0.f, 0.f};
                #pragma unroll
                for (int kc = 0; kc < 4; kc++) {
                    mma16816(s0, Qh[mb][kc], kf[4*kc],   kf[4*kc+1]);
                    mma16816(s1, Qh[mb][kc], kf[4*kc+2], kf[4*kc+3]);
                }
                float2 ba0 = __half22float2(*(const __half2*)&mc[2*mb][0]);
                float2 bb0 = __half22float2(*(const __half2*)&mc[2*mb+1][0]);
                float2 ba1 = __half22float2(*(const __half2*)&mc[2*mb][1]);
                float2 bb1 = __half22float2(*(const __half2*)&mc[2*mb+1][1]);
                float p0 = ex2f(s0[0] + ba0.x);
                float p1 = ex2f(s0[1] + ba0.y);
                float p2 = ex2f(s0[2] + bb0.x);
                float p3 = ex2f(s0[3] + bb0.y);
                float p4 = ex2f(s1[0] + ba1.x);
                float p5 = ex2f(s1[1] + ba1.y);
                float p6 = ex2f(s1[2] + bb1.x);
                float p7 = ex2f(s1[3] + bb1.y);
                lac[mb][0] += p0 + p1 + p4 + p5;
                lac[mb][1] += p2 + p3 + p6 + p7;
                __half2 h0 = __floats2half2_rn(p0, p1);
                __half2 h1 = __floats2half2_rn(p2, p3);
                __half2 h2 = __floats2half2_rn(p4, p5);
                __half2 h3 = __floats2half2_rn(p6, p7);
                Phi[mb][0] = *(uint32_t*)&h0;
                Phi[mb][1] = *(uint32_t*)&h1;
                Phi[mb][2] = *(uint32_t*)&h2;
                Phi[mb][3] = *(uint32_t*)&h3;
            }

            // rotate mask buffers
            #pragma unroll
            for (int r = 0; r < 4; r++) { mc[r][0] = mn[r][0]; mc[r][1] = mn[r][1]; }

            // V fragments for key-block j, shared by both m-blocks
            uint32_t vf[16];
            #pragma unroll
            for (int jj = 0; jj < 4; jj++)
                ldsm4t(vf[4*jj], vf[4*jj+1], vf[4*jj+2], vf[4*jj+3],
                       vb + (16 * j + vrow) * RSB + 32 * jj + vcolb);

            // O += P_j * V_j for both m-blocks
            #pragma unroll
            for (int jj = 0; jj < 4; jj++) {
                #pragma unroll
                for (int mb = 0; mb < 2; mb++) {
                    mma16816(o[mb][2*jj],     Phi[mb], vf[4*jj],   vf[4*jj+1]);
                    mma16816(o[mb][2*jj + 1], Phi[mb], vf[4*jj+2], vf[4*jj+3]);
                }
            }
        }
    }

    // ---- epilogue: reduce l over the quad, normalize, store (2 m-blocks) ----
    #pragma unroll
    for (int mb = 0; mb < 2; mb++) {
        float l0 = lac[mb][0], l1 = lac[mb][1];
        l0 += __shfl_xor_sync(0xffffffffu, l0, 1);
        l0 += __shfl_xor_sync(0xffffffffu, l0, 2);
        l1 += __shfl_xor_sync(0xffffffffu, l1, 1);
        l1 += __shfl_xor_sync(0xffffffffu, l1, 2);
        const float inv0 = 1.0f / l0, inv1 = 1.0f / l1;

        float* O0 = Og + ((size_t)(bh * S_LEN + q0 + qw + mb * 16 + g)) * D_DIM + 2 * qp;
        float* O1 = O0 + 8 * (size_t)D_DIM;
        #pragma unroll
        for (int n = 0; n < 8; n++) {
            *(float2*)(O0 + 8 * n) = make_float2(o[mb][n][0] * inv0, o[mb][n][1] * inv0);
            *(float2*)(O1 + 8 * n) = make_float2(o[mb][n][2] * inv1, o[mb][n][3] * inv1);
        }
    }
}

extern "C" void kernel_launch(void* const* d_in, const int* in_sizes, int n_in,
                              void* d_out, int out_size)
{
    const float* Q = (const float*)d_in[0];
    const float* K = (const float*)d_in[1];
    const float* V = (const float*)d_in[2];
    const int*   M = (const int*)d_in[3];
    float*       O = (float*)d_out;

    cudaFuncSetAttribute(attn_mma, cudaFuncAttributeMaxDynamicSharedMemorySize, SM_TOTAL);

    prep<<<CVT_BLKS + (S_LEN * S_LEN / 4) / 256, 256>>>(Q, K, V, M);
    dim3 grid(BH, S_LEN / QT);   // (16, 32)
    attn_mma<<<grid, NTHR, SM_TOTAL>>>(O);
}

// round 17
// speedup vs baseline: 1.0142x; 1.0142x over previous
#include <cuda_runtime.h>
#include <cuda_fp16.h>
#include <stdint.h>

#define S_LEN 4096
#define D_DIM 64
#define BH    16
#define QT    128
#define KT    64
#define NKT   (S_LEN / KT)
#define NTHR  128
#define RSB   144           // smem row stride (bytes), 16B-aligned, conflict-free for ldmatrix

// smem (bytes): Qh[128][72h] | 2 x { Kh[64][72h] | Vh[64][72h] }
#define SMQ_H   0
#define SMKV    (128 * RSB)
#define KVB     (2 * 64 * RSB)          // 18432 bytes per buffer
#define SM_TOTAL (SMKV + 2 * KVB)       // 55296

// Q pre-scaled by 0.125*log2(e): S = Qs*K^T is already the exp2 argument.
#define EXPC 0.18033688011112042f

// fp16-converted inputs (prologue-filled); mask as additive fp16 bias (0 or -20000)
__device__ __half  g_Qh[(size_t)BH * S_LEN * D_DIM];
__device__ __half  g_Kh[(size_t)BH * S_LEN * D_DIM];
__device__ __half  g_Vh[(size_t)BH * S_LEN * D_DIM];
__device__ __half  g_maskb[(size_t)S_LEN * S_LEN];

// ---------------- helpers ----------------
__device__ __forceinline__ uint32_t su32(const void* p) {
    uint32_t a;
    asm("{ .reg .u64 t; cvta.to.shared.u64 t, %1; cvt.u32.u64 %0, t; }" : "=r"(a) : "l"(p));
    return a;
}
__device__ __forceinline__ void cpa16(uint32_t dst, const void* src) {
    asm volatile("cp.async.cg.shared.global [%0], [%1], 16;" :: "r"(dst), "l"(src));
}
#define CPA_COMMIT() asm volatile("cp.async.commit_group;" ::: "memory")
#define CPA_WAIT(n)  asm volatile("cp.async.wait_group %0;" :: "n"(n) : "memory")

__device__ __forceinline__ void ldsm4(uint32_t& r0, uint32_t& r1, uint32_t& r2, uint32_t& r3, uint32_t a) {
    asm volatile("ldmatrix.sync.aligned.m8n8.x4.shared.b16 {%0,%1,%2,%3}, [%4];"
                 : "=r"(r0), "=r"(r1), "=r"(r2), "=r"(r3) : "r"(a));
}
__device__ __forceinline__ void ldsm4t(uint32_t& r0, uint32_t& r1, uint32_t& r2, uint32_t& r3, uint32_t a) {
    asm volatile("ldmatrix.sync.aligned.m8n8.x4.trans.shared.b16 {%0,%1,%2,%3}, [%4];"
                 : "=r"(r0), "=r"(r1), "=r"(r2), "=r"(r3) : "r"(a));
}
__device__ __forceinline__ void mma16816(float* c, const uint32_t* a, uint32_t b0, uint32_t b1) {
    asm volatile("mma.sync.aligned.m16n8k16.row.col.f32.f16.f16.f32 "
                 "{%0,%1,%2,%3},{%4,%5,%6,%7},{%8,%9},{%0,%1,%2,%3};"
                 : "+f"(c[0]), "+f"(c[1]), "+f"(c[2]), "+f"(c[3])
                 : "r"(a[0]), "r"(a[1]), "r"(a[2]), "r"(a[3]), "r"(b0), "r"(b1));
}
__device__ __forceinline__ float ex2f(float x) {
    float r;
    asm("ex2.approx.f32 %0, %1;" : "=f"(r) : "f"(x));
    return r;
}

// ---------------- fused prologue: cvt (blocks 0..4095) + mask bias (rest) ----------------
#define CVT_BLKS 4096
__global__ void prep(const float* __restrict__ Q, const float* __restrict__ K,
                     const float* __restrict__ V, const int* __restrict__ m) {
    if (blockIdx.x < CVT_BLKS) {
        size_t i = (size_t)blockIdx.x * 256 + threadIdx.x;   // over BH*S*D/4
        float4 q = ((const float4*)Q)[i];
        float4 k = ((const float4*)K)[i];
        float4 v = ((const float4*)V)[i];
        ((__half2*)g_Qh)[2*i]   = __floats2half2_rn(q.x * EXPC, q.y * EXPC);
        ((__half2*)g_Qh)[2*i+1] = __floats2half2_rn(q.z * EXPC, q.w * EXPC);
        ((__half2*)g_Kh)[2*i]   = __floats2half2_rn(k.x, k.y);
        ((__half2*)g_Kh)[2*i+1] = __floats2half2_rn(k.z, k.w);
        ((__half2*)g_Vh)[2*i]   = __floats2half2_rn(v.x, v.y);
        ((__half2*)g_Vh)[2*i+1] = __floats2half2_rn(v.z, v.w);
    } else {
        size_t i = (size_t)(blockIdx.x - CVT_BLKS) * 256 + threadIdx.x;   // over S*S/4
        int4 v = ((const int4*)m)[i];
        const __half zz = __float2half(0.f), bb = __float2half(-20000.f);
        ((__half2*)g_maskb)[2*i]   = __halves2half2(v.x ? bb : zz, v.y ? bb : zz);
        ((__half2*)g_maskb)[2*i+1] = __halves2half2(v.z ? bb : zz, v.w ? bb : zz);
    }
}

// ---- main: FA2-style mma.sync, 4 warps x 32 q-rows, fused stages, chain-interleaved ----
__global__ void __launch_bounds__(NTHR, 2)
attn_mma(float* __restrict__ Og)
{
    extern __shared__ __align__(128) char smem[];
    const uint32_t sb = su32(smem);
    const int tid = threadIdx.x, wid = tid >> 5, lane = tid & 31;
    const int g = lane >> 2, qp = lane & 3;
    const int bh = blockIdx.x;
    const int q0 = blockIdx.y * QT;
    const int qw = wid * 32;                  // warp's q-row base (2 m-blocks of 16)

    // ---- issue Q stage (group 0) ----
    #pragma unroll
    for (int i = 0; i < 8; i++) {
        int cid = i * NTHR + tid;             // 0..1023
        int rr = (cid >> 3) & 127, ch = cid & 7;
        const void* src = g_Qh + ((size_t)(bh * S_LEN + q0 + rr)) * D_DIM + ch * 8;
        cpa16(sb + SMQ_H + rr * RSB + ch * 16, src);
    }
    CPA_COMMIT();
    // ---- issue KV tile 0 (group 1): Kh + Vh ----
    #pragma unroll
    for (int i = 0; i < 8; i++) {
        int cid = i * NTHR + tid;             // 0..1023
        int a = cid >> 9, rr = (cid >> 3) & 63, ch = cid & 7;
        const __half* gk = a ? g_Vh : g_Kh;
        const void* src = gk + ((size_t)(bh * S_LEN + rr)) * D_DIM + ch * 8;
        cpa16(sb + SMKV + a * (64 * RSB) + rr * RSB + ch * 16, src);
    }
    CPA_COMMIT();
    CPA_WAIT(1);                              // Q ready
    __syncthreads();

    // ---- Qh fragments (2 m-blocks) register-resident for the whole kernel ----
    const int arow = lane & 15, acolb = (lane >> 4) * 16;
    uint32_t Qh[2][4][4];
    #pragma unroll
    for (int mb = 0; mb < 2; mb++) {
        const uint32_t qa_base = sb + (qw + mb * 16 + arow) * RSB + acolb;
        #pragma unroll
        for (int kc = 0; kc < 4; kc++)
            ldsm4(Qh[mb][kc][0], Qh[mb][kc][1], Qh[mb][kc][2], Qh[mb][kc][3],
                  qa_base + SMQ_H + kc * 32);
    }

    // lane offsets for K (B-frag, non-trans) and V (B-frag, trans)
    const int krow = (lane & 7) + ((lane >> 4) & 1) * 8;
    const int kcolb = ((lane >> 3) & 1) * 16;
    const int vrow = (lane & 7) + ((lane >> 3) & 1) * 8;
    const int vcolb = ((lane >> 4) & 1) * 16;

    float o[2][8][4];
    #pragma unroll
    for (int mb = 0; mb < 2; mb++)
        #pragma unroll
        for (int n = 0; n < 8; n++)
            #pragma unroll
            for (int j = 0; j < 4; j++) o[mb][n][j] = 0.f;
    float lac[2][2] = {{0.f, 0.f}, {0.f, 0.f}};

    // mask bias row pointers: r = mb*2 + half -> q-row qw + 8r + g
    const __half* mrow[4];
    #pragma unroll
    for (int r = 0; r < 4; r++)
        mrow[r] = g_maskb + (size_t)(q0 + qw + 8 * r + g) * S_LEN + 2 * qp;

    #pragma unroll 1
    for (int kt = 0; kt < NKT; kt++) {
        const int kb = kt * KT;
        const uint32_t kvb = sb + SMKV + (kt & 1) * KVB;
        const uint32_t vb  = kvb + 64 * RSB;

        CPA_WAIT(0);        // tile kt resident
        __syncthreads();    // + everyone done reading the buffer we refill next

        // issue next tile AFTER the barrier (single barrier per tile)
        if (kt + 1 < NKT) {
            #pragma unroll
            for (int i = 0; i < 8; i++) {
                int cid = i * NTHR + tid;
                int a = cid >> 9, rr = (cid >> 3) & 63, ch = cid & 7;
                const __half* gk = a ? g_Vh : g_Kh;
                const void* src = gk + ((size_t)(bh * S_LEN + kb + KT + rr)) * D_DIM + ch * 8;
                cpa16(sb + SMKV + ((kt + 1) & 1) * KVB + a * (64 * RSB) + rr * RSB + ch * 16, src);
            }
            CPA_COMMIT();
        }

        // ---- hoisted mask-bias loads (hide under the first stages) ----
        uint32_t mbl[4][8];
        #pragma unroll
        for (int r = 0; r < 4; r++)
            #pragma unroll
            for (int n = 0; n < 8; n++)
                mbl[r][n] = *(const uint32_t*)(mrow[r] + kb + 8 * n);

        // ---- 4 fused stages; K/V frags shared by both m-blocks; chains interleaved ----
        #pragma unroll
        for (int j = 0; j < 4; j++) {
            // K fragments for key-block j, all 4 d-chunks
            uint32_t kf[16];
            #pragma unroll
            for (int kc = 0; kc < 4; kc++)
                ldsm4(kf[4*kc], kf[4*kc+1], kf[4*kc+2], kf[4*kc+3],
                      kvb + (16 * j + krow) * RSB + kc * 32 + kcolb);

            // All 16 QK MMAs: kc outer, 4 independent chains inner
            // (dependent-MMA distance = 4; accumulation order per chain unchanged)
            float s[2][2][4];
            #pragma unroll
            for (int mb = 0; mb < 2; mb++)
                #pragma unroll
                for (int h = 0; h < 2; h++)
                    #pragma unroll
                    for (int x = 0; x < 4; x++) s[mb][h][x] = 0.f;
            #pragma unroll
            for (int kc = 0; kc < 4; kc++) {
                mma16816(s[0][0], Qh[0][kc], kf[4*kc],   kf[4*kc+1]);
                mma16816(s[0][1], Qh[0][kc], kf[4*kc+2], kf[4*kc+3]);
                mma16816(s[1][0], Qh[1][kc], kf[4*kc],   kf[4*kc+1]);
                mma16816(s[1][1], Qh[1][kc], kf[4*kc+2], kf[4*kc+3]);
            }

            // V fragments for key-block j (s-independent: LDS hides under exp below)
            uint32_t vf[16];
            #pragma unroll
            for (int jj = 0; jj < 4; jj++)
                ldsm4t(vf[4*jj], vf[4*jj+1], vf[4*jj+2], vf[4*jj+3],
                       vb + (16 * j + vrow) * RSB + 32 * jj + vcolb);

            // exp2(s + bias) + pack P for both m-blocks
            uint32_t Phi[2][4];
            #pragma unroll
            for (int mb = 0; mb < 2; mb++) {
                float2 ba0 = __half22float2(*(const __half2*)&mbl[2*mb][2*j]);
                float2 bb0 = __half22float2(*(const __half2*)&mbl[2*mb+1][2*j]);
                float2 ba1 = __half22float2(*(const __half2*)&mbl[2*mb][2*j+1]);
                float2 bb1 = __half22float2(*(const __half2*)&mbl[2*mb+1][2*j+1]);
                float p0 = ex2f(s[mb][0][0] + ba0.x);
                float p1 = ex2f(s[mb][0][1] + ba0.y);
                float p2 = ex2f(s[mb][0][2] + bb0.x);
                float p3 = ex2f(s[mb][0][3] + bb0.y);
                float p4 = ex2f(s[mb][1][0] + ba1.x);
                float p5 = ex2f(s[mb][1][1] + ba1.y);
                float p6 = ex2f(s[mb][1][2] + bb1.x);
                float p7 = ex2f(s[mb][1][3] + bb1.y);
                lac[mb][0] += p0 + p1 + p4 + p5;
                lac[mb][1] += p2 + p3 + p6 + p7;
                __half2 h0 = __floats2half2_rn(p0, p1);
                __half2 h1 = __floats2half2_rn(p2, p3);
                __half2 h2 = __floats2half2_rn(p4, p5);
                __half2 h3 = __floats2half2_rn(p6, p7);
                Phi[mb][0] = *(uint32_t*)&h0;
                Phi[mb][1] = *(uint32_t*)&h1;
                Phi[mb][2] = *(uint32_t*)&h2;
                Phi[mb][3] = *(uint32_t*)&h3;
            }

            // O += P_j * V_j for both m-blocks (8 independent accumulators)
            #pragma unroll
            for (int jj = 0; jj < 4; jj++) {
                #pragma unroll
                for (int mb = 0; mb < 2; mb++) {
                    mma16816(o[mb][2*jj],     Phi[mb], vf[4*jj],   vf[4*jj+1]);
                    mma16816(o[mb][2*jj + 1], Phi[mb], vf[4*jj+2], vf[4*jj+3]);
                }
            }
        }
    }

    // ---- epilogue: reduce l over the quad, normalize, store (2 m-blocks) ----
    #pragma unroll
    for (int mb = 0; mb < 2; mb++) {
        float l0 = lac[mb][0], l1 = lac[mb][1];
        l0 += __shfl_xor_sync(0xffffffffu, l0, 1);
        l0 += __shfl_xor_sync(0xffffffffu, l0, 2);
        l1 += __shfl_xor_sync(0xffffffffu, l1, 1);
        l1 += __shfl_xor_sync(0xffffffffu, l1, 2);
        const float inv0 = 1.0f / l0, inv1 = 1.0f / l1;

        float* O0 = Og + ((size_t)(bh * S_LEN + q0 + qw + mb * 16 + g)) * D_DIM + 2 * qp;
        float* O1 = O0 + 8 * (size_t)D_DIM;
        #pragma unroll
        for (int n = 0; n < 8; n++) {
            *(float2*)(O0 + 8 * n) = make_float2(o[mb][n][0] * inv0, o[mb][n][1] * inv0);
            *(float2*)(O1 + 8 * n) = make_float2(o[mb][n][2] * inv1, o[mb][n][3] * inv1);
        }
    }
}

extern "C" void kernel_launch(void* const* d_in, const int* in_sizes, int n_in,
                              void* d_out, int out_size)
{
    const float* Q = (const float*)d_in[0];
    const float* K = (const float*)d_in[1];
    const float* V = (const float*)d_in[2];
    const int*   M = (const int*)d_in[3];
    float*       O = (float*)d_out;

    cudaFuncSetAttribute(attn_mma, cudaFuncAttributeMaxDynamicSharedMemorySize, SM_TOTAL);

    prep<<<CVT_BLKS + (S_LEN * S_LEN / 4) / 256, 256>>>(Q, K, V, M);
    dim3 grid(BH, S_LEN / QT);   // (16, 32)
    attn_mma<<<grid, NTHR, SM_TOTAL>>>(O);
}